// round 15
// baseline (speedup 1.0000x reference)
#include <cuda_runtime.h>
#include <cuda_fp16.h>
#include <cstdint>

#define EDIM   512
#define MROWS  8192
#define NCHUNK 16
#define S_PER_CHUNK 128
#define S_TILE 64

// ---------------- scratch (no allocation allowed) ----------------
__device__ __half g_qh[MROWS * EDIM];
__device__ __half g_kh[MROWS * EDIM];
__device__ __half g_vh[MROWS * EDIM];
__device__ float g_part[32 * NCHUNK * 4224];
__device__ __half g_Mh[32 * 4096];
__device__ float g_ksum[32 * 64];
__device__ float g_vsum[32 * 64];
__device__ unsigned g_cnt[32];             // zero-init; self-resetting
__device__ __half g_xh[MROWS * EDIM];      // query fp16
__device__ __half g_wh[4 * EDIM * EDIM];   // Wq|Wk|Wv|Wo fp16
__device__ __half g_ah[MROWS * EDIM];      // attention-out fp16
__device__ float g_bp[4 * EDIM];

// =================== helpers ===================
__device__ __forceinline__ uint32_t smem_u32(const void* p) {
    uint32_t a;
    asm("{ .reg .u64 t; cvta.to.shared.u64 t, %1; cvt.u32.u64 %0, t; }" : "=r"(a) : "l"(p));
    return a;
}
__device__ __forceinline__ uint32_t sw128(uint32_t off) { return off ^ ((off >> 3) & 0x70); }

__device__ __forceinline__ uint32_t pack2h(float a, float b) {
    __half2 h = __floats2half2_rn(a, b);
    return *(uint32_t*)&h;
}
#define LDSM4(r, addr) \
    asm volatile("ldmatrix.sync.aligned.m8n8.x4.shared.b16 {%0,%1,%2,%3}, [%4];" \
        : "=r"((r)[0]), "=r"((r)[1]), "=r"((r)[2]), "=r"((r)[3]) : "r"(addr))
#define LDSM4T(r, addr) \
    asm volatile("ldmatrix.sync.aligned.m8n8.x4.trans.shared.b16 {%0,%1,%2,%3}, [%4];" \
        : "=r"((r)[0]), "=r"((r)[1]), "=r"((r)[2]), "=r"((r)[3]) : "r"(addr))
#define MMA16816(d, a, b0, b1) \
    asm volatile("mma.sync.aligned.m16n8k16.row.col.f32.f16.f16.f32 " \
        "{%0,%1,%2,%3},{%4,%5,%6,%7},{%8,%9},{%0,%1,%2,%3};" \
        : "+f"((d)[0]), "+f"((d)[1]), "+f"((d)[2]), "+f"((d)[3]) \
        : "r"((a)[0]), "r"((a)[1]), "r"((a)[2]), "r"((a)[3]), "r"(b0), "r"(b1))
#define CP16(saddr, gptr) \
    asm volatile("cp.async.cg.shared.global [%0], [%1], 16;" :: "r"(saddr), "l"(gptr))
#define CP_COMMIT() asm volatile("cp.async.commit_group;" ::: "memory")
#define CP_WAIT2()  asm volatile("cp.async.wait_group 2;" ::: "memory")
#define CP_WAIT1()  asm volatile("cp.async.wait_group 1;" ::: "memory")
#define CP_WAIT0()  asm volatile("cp.async.wait_group 0;" ::: "memory")

// ------------- one fused fp32 -> fp16 conversion for ALL operands -------------
#define NQ4  (MROWS * EDIM / 4)
#define NW4  (EDIM * EDIM / 4)
__global__ void split_all_kernel(const float4* __restrict__ q,
                                 const float4* __restrict__ wq, const float4* __restrict__ wk,
                                 const float4* __restrict__ wv, const float4* __restrict__ wo,
                                 const float* __restrict__ bq, const float* __restrict__ bk,
                                 const float* __restrict__ bv, const float* __restrict__ bo)
{
    const int i = blockIdx.x * blockDim.x + threadIdx.x;
    const int total = NQ4 + 4 * NW4;
    if (i < NQ4) {
        const float4 x = q[i];
        ((uint2*)g_xh)[i] = make_uint2(pack2h(x.x, x.y), pack2h(x.z, x.w));
    } else if (i < total) {
        const int j = i - NQ4;
        const int w = j / NW4, off = j % NW4;
        const float4* src = (w == 0) ? wq : (w == 1) ? wk : (w == 2) ? wv : wo;
        const float4 x = src[off];
        ((uint2*)g_wh)[j] = make_uint2(pack2h(x.x, x.y), pack2h(x.z, x.w));
    } else if (i < total + EDIM) {
        const int t = i - total;
        g_bp[t] = bq[t];
        g_bp[EDIM + t] = bk[t];
        g_bp[2 * EDIM + t] = bv[t];
        g_bp[3 * EDIM + t] = bo[t];
    }
}

// ======== fp16 single-pass warp-MMA GEMM, 3-stage cp.async pipeline ========
#define STAGE_BYTES 32768
#define SMEM_DYN (3 * STAGE_BYTES)

extern __shared__ __align__(1024) char dynsmem[];

__global__ __launch_bounds__(256, 2)
void gemm_f16(const __half* __restrict__ Ah,
              int wbase, int n_soft, int fp16_out,
              void* __restrict__ out0, void* __restrict__ out1, void* __restrict__ out2)
{
    const uint32_t sbase = smem_u32(dynsmem);
    const int tid = threadIdx.x;
    const int wid = tid >> 5, lid = tid & 31;
    const int warp_m = wid >> 2;
    const int warp_n = wid & 3;
    const int nb = blockIdx.x;
    const int bm = blockIdx.y << 7;
    const int bn = (nb & 3) << 7;
    const int sel = nb >> 2;
    void* outp = (sel == 0) ? out0 : ((sel == 1) ? out1 : out2);
    const int wrow = wbase + nb * 128;
    const int fuse_sm = (sel < n_soft);

    int cp_r[4], cp_cg[4];
    uint32_t cp_soff[4];
    #pragma unroll
    for (int it = 0; it < 4; ++it) {
        const int g = tid + it * 256;
        cp_r[it] = g >> 3;
        cp_cg[it] = g & 7;
        cp_soff[it] = sw128((uint32_t)(cp_r[it] * 128 + cp_cg[it] * 16));
    }

    float acc[4][4][4] = {};
    const int a_row = warp_m * 64 + (lid & 7) + ((lid >> 3) & 1) * 8;
    const int a_kb  = (lid >> 4) * 16;
    const int b_row = warp_n * 32 + (lid & 7) + (lid >> 4) * 8;
    const int b_kb  = ((lid >> 3) & 1) * 16;

    auto issue = [&](int c, int buf) {
        const uint32_t ah = sbase + buf * STAGE_BYTES;
        const uint32_t bh = ah + 16384;
        const int kof = c * 64;
        #pragma unroll
        for (int it = 0; it < 4; ++it) {
            const size_t aoff = (size_t)(bm + cp_r[it]) * EDIM + kof + cp_cg[it] * 8;
            const size_t boff = (size_t)(wrow + cp_r[it]) * EDIM + kof + cp_cg[it] * 8;
            CP16(ah + cp_soff[it], Ah + aoff);
            CP16(bh + cp_soff[it], g_wh + boff);
        }
        CP_COMMIT();
    };

    issue(0, 0);
    issue(1, 1);

    for (int c = 0; c < 8; ++c) {
        if (c + 2 < 8) { issue(c + 2, (c + 2) % 3); CP_WAIT2(); }
        else if (c + 1 < 8) { CP_WAIT1(); }
        else { CP_WAIT0(); }
        __syncthreads();

        const uint32_t ah = sbase + (c % 3) * STAGE_BYTES;
        const uint32_t bh = ah + 16384;

        #pragma unroll
        for (int ks = 0; ks < 4; ++ks) {
            uint32_t Ahf[4][4];
            #pragma unroll
            for (int mt = 0; mt < 4; ++mt) {
                const uint32_t off = sw128((uint32_t)((a_row + mt * 16) * 128 + ks * 32 + a_kb));
                LDSM4(Ahf[mt], ah + off);
            }
            uint32_t Bh[8];
            #pragma unroll
            for (int np = 0; np < 2; ++np) {
                const uint32_t off = sw128((uint32_t)((b_row + np * 16) * 128 + ks * 32 + b_kb));
                LDSM4(&Bh[np * 4], bh + off);
            }
            #pragma unroll
            for (int mt = 0; mt < 4; ++mt)
                #pragma unroll
                for (int nt = 0; nt < 4; ++nt)
                    MMA16816(acc[mt][nt], Ahf[mt], Bh[nt * 2], Bh[nt * 2 + 1]);
        }
        __syncthreads();
    }

    if (fuse_sm) {
        float* sm = (float*)dynsmem;   // 128 rows x stride 130
        #pragma unroll
        for (int mt = 0; mt < 4; ++mt) {
            const int r0 = warp_m * 64 + mt * 16 + (lid >> 2);
            #pragma unroll
            for (int nt = 0; nt < 4; ++nt) {
                const int cit = warp_n * 32 + nt * 8 + ((lid & 3) << 1);
                const float b0 = g_bp[wrow + cit], b1 = g_bp[wrow + cit + 1];
                sm[r0 * 130 + cit]           = acc[mt][nt][0] + b0;
                sm[r0 * 130 + cit + 1]       = acc[mt][nt][1] + b1;
                sm[(r0 + 8) * 130 + cit]     = acc[mt][nt][2] + b0;
                sm[(r0 + 8) * 130 + cit + 1] = acc[mt][nt][3] + b1;
            }
        }
        __syncthreads();
        __half* op = (__half*)outp;
        #pragma unroll
        for (int rr = 0; rr < 16; ++rr) {
            const int r = wid * 16 + rr;
            #pragma unroll
            for (int g = 0; g < 2; ++g) {
                float a = sm[r * 130 + g * 64 + lid];
                float b = sm[r * 130 + g * 64 + lid + 32];
                float m = fmaxf(a, b);
                #pragma unroll
                for (int o = 16; o > 0; o >>= 1)
                    m = fmaxf(m, __shfl_xor_sync(0xffffffffu, m, o));
                float ea = __expf(a - m), eb = __expf(b - m);
                float s = ea + eb;
                #pragma unroll
                for (int o = 16; o > 0; o >>= 1)
                    s += __shfl_xor_sync(0xffffffffu, s, o);
                const float inv = 1.0f / s;
                __half* p = op + (size_t)(bm + r) * EDIM + bn + g * 64;
                p[lid]      = __float2half_rn(ea * inv);
                p[lid + 32] = __float2half_rn(eb * inv);
            }
        }
    } else if (fp16_out) {
        __half* op = (__half*)outp;
        #pragma unroll
        for (int mt = 0; mt < 4; ++mt) {
            const int r0 = bm + warp_m * 64 + mt * 16 + (lid >> 2);
            #pragma unroll
            for (int nt = 0; nt < 4; ++nt) {
                const int cit = warp_n * 32 + nt * 8 + ((lid & 3) << 1);
                const float b0 = g_bp[wrow + cit], b1 = g_bp[wrow + cit + 1];
                const int col = bn + cit;
                *(__half2*)(op + (size_t)r0 * EDIM + col) =
                    __floats2half2_rn(acc[mt][nt][0] + b0, acc[mt][nt][1] + b1);
                *(__half2*)(op + (size_t)(r0 + 8) * EDIM + col) =
                    __floats2half2_rn(acc[mt][nt][2] + b0, acc[mt][nt][3] + b1);
            }
        }
    } else {
        float* op = (float*)outp;
        #pragma unroll
        for (int mt = 0; mt < 4; ++mt) {
            const int r0 = bm + warp_m * 64 + mt * 16 + (lid >> 2);
            #pragma unroll
            for (int nt = 0; nt < 4; ++nt) {
                const int cit = warp_n * 32 + nt * 8 + ((lid & 3) << 1);
                const float b0 = g_bp[wrow + cit], b1 = g_bp[wrow + cit + 1];
                const int col = bn + cit;
                *(float2*)(op + (size_t)r0 * EDIM + col) =
                    make_float2(acc[mt][nt][0] + b0, acc[mt][nt][1] + b1);
                *(float2*)(op + (size_t)(r0 + 8) * EDIM + col) =
                    make_float2(acc[mt][nt][2] + b0, acc[mt][nt][3] + b1);
            }
        }
    }
}

// ======== MMA stats with fused last-block reduction ========
// grid (NCHUNK, 32) = 512 blocks; NT=2 tiles per chunk, double buffered.
__global__ __launch_bounds__(256, 2)
void stats_mma_kernel()
{
    __shared__ __align__(1024) char smem[2 * 16384];
    __shared__ int s_last;
    const int n = blockIdx.y, b = n >> 3, h = n & 7;
    const int s0 = blockIdx.x * S_PER_CHUNK;
    const uint32_t sb = smem_u32(smem);
    const int tid = threadIdx.x, wid = tid >> 5, lid = tid & 31;
    const int warp_m = wid >> 2;
    const int warp_n = wid & 3;

    auto issue = [&](int t, int buf) {
        const uint32_t kb = sb + buf * 16384;
        const uint32_t vb = kb + 8192;
        #pragma unroll
        for (int it = 0; it < 2; ++it) {
            const int g = tid + it * 256;
            const int r = g >> 3, cg = g & 7;
            const int s = s0 + t * S_TILE + r;
            const size_t go = (size_t)(s * 4 + b) * EDIM + h * 64 + cg * 8;
            const uint32_t so = sw128((uint32_t)(r * 128 + cg * 16));
            CP16(kb + so, g_kh + go);
            CP16(vb + so, g_vh + go);
        }
        CP_COMMIT();
    };

    float acc[2][2][4] = {};
    float colsum = 0.f;   // threads 0-127: ksum half, 128-255: vsum half

    const int a_row = (lid & 7) + ((lid >> 4) & 1) * 8;
    const int a_by  = ((lid >> 3) & 1) * 16;
    const int b_row = (lid & 7) + ((lid >> 3) & 1) * 8;
    const int b_by  = ((lid >> 4) & 1) * 16;

    issue(0, 0);
    issue(1, 1);

    const int NT = S_PER_CHUNK / S_TILE;   // 2
    for (int t = 0; t < NT; ++t) {
        if (t < NT - 1) CP_WAIT1(); else CP_WAIT0();
        __syncthreads();
        const uint32_t kb = sb + (t & 1) * 16384;
        const uint32_t vb = kb + 8192;

        #pragma unroll
        for (int ks = 0; ks < 4; ++ks) {
            uint32_t Af[2][4];
            #pragma unroll
            for (int mt = 0; mt < 2; ++mt) {
                const uint32_t off = sw128((uint32_t)((ks * 16 + a_row) * 128
                                     + warp_m * 64 + mt * 32 + a_by));
                LDSM4T(Af[mt], kb + off);
            }
            uint32_t Bf[4];
            {
                const uint32_t off = sw128((uint32_t)((ks * 16 + b_row) * 128
                                     + warp_n * 32 + b_by));
                LDSM4T(Bf, vb + off);
            }
            #pragma unroll
            for (int mt = 0; mt < 2; ++mt)
                #pragma unroll
                for (int nt = 0; nt < 2; ++nt)
                    MMA16816(acc[mt][nt], Af[mt], Bf[nt * 2], Bf[nt * 2 + 1]);
        }

        // column sums: all 256 threads; 2 threads per column, 32 rows each
        {
            const uint32_t base = (tid < 128) ? kb : vb;
            const int tt = tid & 127;
            const int d  = tt >> 1;        // column 0..63
            const int rh = (tt & 1) * 32;  // row half
            float s = 0.f;
            #pragma unroll
            for (int r = 0; r < 32; ++r)
                s += __half2float(*(const __half*)(smem + (base - sb)
                        + sw128((uint32_t)((rh + r) * 128 + d * 2))));
            colsum += s;
        }
        __syncthreads();
    }

    float* pb = g_part + (size_t)(n * NCHUNK + blockIdx.x) * 4224;
    #pragma unroll
    for (int mt = 0; mt < 2; ++mt) {
        const int d1 = warp_m * 32 + mt * 16 + (lid >> 2);
        #pragma unroll
        for (int nt = 0; nt < 2; ++nt) {
            const int d2 = warp_n * 16 + nt * 8 + ((lid & 3) << 1);
            *(float2*)(pb + d1 * 64 + d2)       = make_float2(acc[mt][nt][0], acc[mt][nt][1]);
            *(float2*)(pb + (d1 + 8) * 64 + d2) = make_float2(acc[mt][nt][2], acc[mt][nt][3]);
        }
    }
    // combine row halves: partner lanes 2d, 2d+1 are adjacent
    colsum += __shfl_xor_sync(0xffffffffu, colsum, 1);
    if (((tid & 127) & 1) == 0) {
        const int d = (tid & 127) >> 1;
        if (tid < 128) pb[4096 + d] = colsum;
        else           pb[4160 + d] = colsum;
    }

    __syncthreads();
    __threadfence();
    if (tid == 0) {
        const unsigned v = atomicAdd(&g_cnt[n], 1u);
        s_last = (v == NCHUNK - 1);
    }
    __syncthreads();
    if (s_last) {
        for (int j = tid; j < 4224; j += 256) {
            float s = 0.f;
            #pragma unroll
            for (int c = 0; c < NCHUNK; ++c)
                s += g_part[(size_t)(n * NCHUNK + c) * 4224 + j];
            if (j < 4096)       g_Mh[n * 4096 + j] = __float2half_rn(s);
            else if (j < 4160)  g_ksum[n * 64 + (j - 4096)] = s;
            else                g_vsum[n * 64 + (j - 4160)] = s;
        }
        if (tid == 0) g_cnt[n] = 0;
    }
}

// ======== MMA combine: a = (62*Vsum + 2*q@M) / (62*2048 + 2*q.Ksum), fp16 ====
// grid (32, 32): 64 l-rows x 64 d2 per block. Coalesced stores via smem staging.
#define CST 144   // staging row stride in bytes
__global__ __launch_bounds__(256)
void combine_mma_kernel()
{
    __shared__ __align__(1024) char smem[8192 + 8192];  // q 8K | M 8K; reused as stage
    __shared__ float ksum_s[64], vsum_s[64], inv_s[64];
    const int n = blockIdx.y, b = n >> 3, h = n & 7;
    const int l0 = blockIdx.x << 6;
    const uint32_t qb = smem_u32(smem);
    const uint32_t mb = qb + 8192;
    const int tid = threadIdx.x, wid = tid >> 5, lid = tid & 31;
    const int warp_m = wid >> 1;   // 0..3 (16 l each)
    const int warp_n = wid & 1;    // 0..1 (32 d2 each)

    #pragma unroll
    for (int it = 0; it < 2; ++it) {
        const int g = tid + it * 256;
        const int r = g >> 3, cg = g & 7;
        const size_t go = (size_t)((l0 + r) * 4 + b) * EDIM + h * 64 + cg * 8;
        const uint32_t so = sw128((uint32_t)(r * 128 + cg * 16));
        CP16(qb + so, g_qh + go);
        CP16(mb + so, g_Mh + (size_t)n * 4096 + r * 64 + cg * 8);
    }
    CP_COMMIT();
    if (tid < 64) { ksum_s[tid] = g_ksum[n * 64 + tid]; vsum_s[tid] = g_vsum[n * 64 + tid]; }
    CP_WAIT0();
    __syncthreads();

    // denominator: 4 threads per row, 2x LDS.128, shfl-combine
    {
        const int row = tid >> 2;
        const int qr  = tid & 3;
        float s = 0.f;
        #pragma unroll
        for (int hh = 0; hh < 2; ++hh) {
            const uint32_t off = sw128((uint32_t)(row * 128 + qr * 32 + hh * 16));
            const uint4 v = *(const uint4*)(smem + off);
            const uint32_t w[4] = {v.x, v.y, v.z, v.w};
            const int dbase = qr * 16 + hh * 8;
            #pragma unroll
            for (int p = 0; p < 4; ++p) {
                const float2 f = __half22float2(*(const __half2*)&w[p]);
                s += f.x * ksum_s[dbase + p * 2] + f.y * ksum_s[dbase + p * 2 + 1];
            }
        }
        s += __shfl_xor_sync(0xffffffffu, s, 1);
        s += __shfl_xor_sync(0xffffffffu, s, 2);
        if (qr == 0) inv_s[row] = 1.0f / (126976.0f + 2.0f * s);
    }
    __syncthreads();

    // q @ M via MMA: 64x64x64; warp tile 16 l x 32 d2
    float acc[4][4] = {};
    const int a_row = warp_m * 16 + (lid & 7) + ((lid >> 3) & 1) * 8;
    const int a_kb  = (lid >> 4) * 16;
    const int b_row = (lid & 7) + ((lid >> 3) & 1) * 8;
    const int b_by  = ((lid >> 4) & 1) * 16;

    #pragma unroll
    for (int ks = 0; ks < 4; ++ks) {
        uint32_t Af[4];
        LDSM4(Af, qb + sw128((uint32_t)(a_row * 128 + ks * 32 + a_kb)));
        uint32_t Bf[2][4];
        #pragma unroll
        for (int hf = 0; hf < 2; ++hf)
            LDSM4T(Bf[hf], mb + sw128((uint32_t)((ks * 16 + b_row) * 128
                                 + warp_n * 64 + hf * 32 + b_by)));
        #pragma unroll
        for (int nt = 0; nt < 4; ++nt)
            MMA16816(acc[nt], Af, Bf[nt >> 1][(nt & 1) * 2], Bf[nt >> 1][(nt & 1) * 2 + 1]);
    }

    __syncthreads();   // all q/M smem reads done; reuse as staging
    {
        const int l = warp_m * 16 + (lid >> 2);
        const float i0 = inv_s[l], i1 = inv_s[l + 8];
        #pragma unroll
        for (int nt = 0; nt < 4; ++nt) {
            const int d2 = warp_n * 32 + nt * 8 + ((lid & 3) << 1);
            const float v0 = 62.f * vsum_s[d2], v1 = 62.f * vsum_s[d2 + 1];
            *(uint32_t*)(smem + l * CST + d2 * 2) =
                pack2h((v0 + 2.f * acc[nt][0]) * i0, (v1 + 2.f * acc[nt][1]) * i0);
            *(uint32_t*)(smem + (l + 8) * CST + d2 * 2) =
                pack2h((v0 + 2.f * acc[nt][2]) * i1, (v1 + 2.f * acc[nt][3]) * i1);
        }
    }
    __syncthreads();
    // coalesced copy out: 64 rows x 128B payload
    #pragma unroll
    for (int it = 0; it < 2; ++it) {
        const int idx = tid + it * 256;        // 0..511
        const int row = idx >> 3, o16 = idx & 7;
        const uint4 v = *(const uint4*)(smem + row * CST + o16 * 16);
        *(uint4*)(g_ah + (size_t)((l0 + row) * 4 + b) * EDIM + h * 64 + o16 * 8) = v;
    }
}

// ---------------- launch -----------------------------------------------------
extern "C" void kernel_launch(void* const* d_in, const int* in_sizes, int n_in,
                              void* d_out, int out_size)
{
    const float* query = (const float*)d_in[0];
    const float* Wq = (const float*)d_in[1];
    const float* bq = (const float*)d_in[2];
    const float* Wk = (const float*)d_in[3];
    const float* bk = (const float*)d_in[4];
    const float* Wv = (const float*)d_in[5];
    const float* bv = (const float*)d_in[6];
    const float* Wo = (const float*)d_in[7];
    const float* bo = (const float*)d_in[8];
    float* out = (float*)d_out;

    __half *qp, *kp, *vp, *xh, *ahp;
    cudaGetSymbolAddress((void**)&qp, g_qh);
    cudaGetSymbolAddress((void**)&kp, g_kh);
    cudaGetSymbolAddress((void**)&vp, g_vh);
    cudaGetSymbolAddress((void**)&xh, g_xh);
    cudaGetSymbolAddress((void**)&ahp, g_ah);

    static cudaStream_t s1 = nullptr;
    static cudaEvent_t ev_split = nullptr, ev_q = nullptr;
    if (!s1) {
        cudaStreamCreateWithFlags(&s1, cudaStreamNonBlocking);
        cudaEventCreateWithFlags(&ev_split, cudaEventDisableTiming);
        cudaEventCreateWithFlags(&ev_q, cudaEventDisableTiming);
        cudaFuncSetAttribute(gemm_f16, cudaFuncAttributeMaxDynamicSharedMemorySize, SMEM_DYN);
    }

    const int total = NQ4 + 4 * NW4 + EDIM;
    split_all_kernel<<<(total + 255) / 256, 256>>>(
        (const float4*)query, (const float4*)Wq, (const float4*)Wk,
        (const float4*)Wv, (const float4*)Wo, bq, bk, bv, bo);

    // fork: Q GEMM (softmax) on side stream, concurrent with KV GEMM + stats
    cudaEventRecord(ev_split, 0);
    cudaStreamWaitEvent(s1, ev_split, 0);
    gemm_f16<<<dim3(4, 64), 256, SMEM_DYN, s1>>>(xh, 0, 1, 1, qp, qp, qp);
    cudaEventRecord(ev_q, s1);

    // legacy stream: K (softmax) + V GEMM, then stats
    gemm_f16<<<dim3(8, 64), 256, SMEM_DYN>>>(xh, 512, 1, 1, kp, vp, vp);
    stats_mma_kernel<<<dim3(NCHUNK, 32), 256>>>();

    // join: combine needs q + stats
    cudaStreamWaitEvent(0, ev_q, 0);
    combine_mma_kernel<<<dim3(32, 32), 256>>>();
    // O GEMM (fp32 output)
    gemm_f16<<<dim3(4, 64), 256, SMEM_DYN>>>(ahp, 3 * EDIM, 0, 0, out, out, out);
}

// round 16
// speedup vs baseline: 1.0218x; 1.0218x over previous
#include <cuda_runtime.h>
#include <cuda_fp16.h>
#include <cstdint>

#define EDIM   512
#define MROWS  8192
#define NCHUNK 8
#define S_PER_CHUNK 256
#define S_TILE 64

// ---------------- scratch (no allocation allowed) ----------------
__device__ __half g_qh[MROWS * EDIM];
__device__ __half g_kh[MROWS * EDIM];
__device__ __half g_vh[MROWS * EDIM];
__device__ float g_part[32 * NCHUNK * 4224];
__device__ __half g_Mh[32 * 4096];
__device__ float g_ksum[32 * 64];
__device__ float g_vsum[32 * 64];
__device__ unsigned g_cnt[32];             // zero-init; self-resetting
__device__ __half g_xh[MROWS * EDIM];      // query fp16
__device__ __half g_wh[4 * EDIM * EDIM];   // Wq|Wk|Wv|Wo fp16
__device__ __half g_ah[MROWS * EDIM];      // attention-out fp16
__device__ float g_bp[4 * EDIM];

// =================== helpers ===================
__device__ __forceinline__ uint32_t smem_u32(const void* p) {
    uint32_t a;
    asm("{ .reg .u64 t; cvta.to.shared.u64 t, %1; cvt.u32.u64 %0, t; }" : "=r"(a) : "l"(p));
    return a;
}
__device__ __forceinline__ uint32_t sw128(uint32_t off) { return off ^ ((off >> 3) & 0x70); }

__device__ __forceinline__ uint32_t pack2h(float a, float b) {
    __half2 h = __floats2half2_rn(a, b);
    return *(uint32_t*)&h;
}
#define LDSM4(r, addr) \
    asm volatile("ldmatrix.sync.aligned.m8n8.x4.shared.b16 {%0,%1,%2,%3}, [%4];" \
        : "=r"((r)[0]), "=r"((r)[1]), "=r"((r)[2]), "=r"((r)[3]) : "r"(addr))
#define LDSM4T(r, addr) \
    asm volatile("ldmatrix.sync.aligned.m8n8.x4.trans.shared.b16 {%0,%1,%2,%3}, [%4];" \
        : "=r"((r)[0]), "=r"((r)[1]), "=r"((r)[2]), "=r"((r)[3]) : "r"(addr))
#define MMA16816(d, a, b0, b1) \
    asm volatile("mma.sync.aligned.m16n8k16.row.col.f32.f16.f16.f32 " \
        "{%0,%1,%2,%3},{%4,%5,%6,%7},{%8,%9},{%0,%1,%2,%3};" \
        : "+f"((d)[0]), "+f"((d)[1]), "+f"((d)[2]), "+f"((d)[3]) \
        : "r"((a)[0]), "r"((a)[1]), "r"((a)[2]), "r"((a)[3]), "r"(b0), "r"(b1))
#define CP16(saddr, gptr) \
    asm volatile("cp.async.cg.shared.global [%0], [%1], 16;" :: "r"(saddr), "l"(gptr))
#define CP_COMMIT() asm volatile("cp.async.commit_group;" ::: "memory")
#define CP_WAIT2()  asm volatile("cp.async.wait_group 2;" ::: "memory")
#define CP_WAIT1()  asm volatile("cp.async.wait_group 1;" ::: "memory")
#define CP_WAIT0()  asm volatile("cp.async.wait_group 0;" ::: "memory")

// ------------- one fused fp32 -> fp16 conversion for ALL operands -------------
#define NQ4  (MROWS * EDIM / 4)
#define NW4  (EDIM * EDIM / 4)
__global__ void split_all_kernel(const float4* __restrict__ q,
                                 const float4* __restrict__ wq, const float4* __restrict__ wk,
                                 const float4* __restrict__ wv, const float4* __restrict__ wo,
                                 const float* __restrict__ bq, const float* __restrict__ bk,
                                 const float* __restrict__ bv, const float* __restrict__ bo)
{
    const int i = blockIdx.x * blockDim.x + threadIdx.x;
    const int total = NQ4 + 4 * NW4;
    if (i < NQ4) {
        const float4 x = q[i];
        ((uint2*)g_xh)[i] = make_uint2(pack2h(x.x, x.y), pack2h(x.z, x.w));
    } else if (i < total) {
        const int j = i - NQ4;
        const int w = j / NW4, off = j % NW4;
        const float4* src = (w == 0) ? wq : (w == 1) ? wk : (w == 2) ? wv : wo;
        const float4 x = src[off];
        ((uint2*)g_wh)[j] = make_uint2(pack2h(x.x, x.y), pack2h(x.z, x.w));
    } else if (i < total + EDIM) {
        const int t = i - total;
        g_bp[t] = bq[t];
        g_bp[EDIM + t] = bk[t];
        g_bp[2 * EDIM + t] = bv[t];
        g_bp[3 * EDIM + t] = bo[t];
    }
}

// ======== fp16 single-pass warp-MMA GEMM, 3-stage cp.async pipeline ========
#define STAGE_BYTES 32768
#define SMEM_DYN (3 * STAGE_BYTES)

extern __shared__ __align__(1024) char dynsmem[];

__global__ __launch_bounds__(256, 2)
void gemm_f16(const __half* __restrict__ Ah,
              int wbase, int n_soft, int fp16_out,
              void* __restrict__ out0, void* __restrict__ out1, void* __restrict__ out2)
{
    const uint32_t sbase = smem_u32(dynsmem);
    const int tid = threadIdx.x;
    const int wid = tid >> 5, lid = tid & 31;
    const int warp_m = wid >> 2;
    const int warp_n = wid & 3;
    const int nb = blockIdx.x;
    const int bm = blockIdx.y << 7;
    const int bn = (nb & 3) << 7;
    const int sel = nb >> 2;
    void* outp = (sel == 0) ? out0 : ((sel == 1) ? out1 : out2);
    const int wrow = wbase + nb * 128;
    const int fuse_sm = (sel < n_soft);

    int cp_r[4], cp_cg[4];
    uint32_t cp_soff[4];
    #pragma unroll
    for (int it = 0; it < 4; ++it) {
        const int g = tid + it * 256;
        cp_r[it] = g >> 3;
        cp_cg[it] = g & 7;
        cp_soff[it] = sw128((uint32_t)(cp_r[it] * 128 + cp_cg[it] * 16));
    }

    float acc[4][4][4] = {};
    const int a_row = warp_m * 64 + (lid & 7) + ((lid >> 3) & 1) * 8;
    const int a_kb  = (lid >> 4) * 16;
    const int b_row = warp_n * 32 + (lid & 7) + (lid >> 4) * 8;
    const int b_kb  = ((lid >> 3) & 1) * 16;

    auto issue = [&](int c, int buf) {
        const uint32_t ah = sbase + buf * STAGE_BYTES;
        const uint32_t bh = ah + 16384;
        const int kof = c * 64;
        #pragma unroll
        for (int it = 0; it < 4; ++it) {
            const size_t aoff = (size_t)(bm + cp_r[it]) * EDIM + kof + cp_cg[it] * 8;
            const size_t boff = (size_t)(wrow + cp_r[it]) * EDIM + kof + cp_cg[it] * 8;
            CP16(ah + cp_soff[it], Ah + aoff);
            CP16(bh + cp_soff[it], g_wh + boff);
        }
        CP_COMMIT();
    };

    issue(0, 0);
    issue(1, 1);

    for (int c = 0; c < 8; ++c) {
        if (c + 2 < 8) { issue(c + 2, (c + 2) % 3); CP_WAIT2(); }
        else if (c + 1 < 8) { CP_WAIT1(); }
        else { CP_WAIT0(); }
        __syncthreads();

        const uint32_t ah = sbase + (c % 3) * STAGE_BYTES;
        const uint32_t bh = ah + 16384;

        #pragma unroll
        for (int ks = 0; ks < 4; ++ks) {
            uint32_t Ahf[4][4];
            #pragma unroll
            for (int mt = 0; mt < 4; ++mt) {
                const uint32_t off = sw128((uint32_t)((a_row + mt * 16) * 128 + ks * 32 + a_kb));
                LDSM4(Ahf[mt], ah + off);
            }
            uint32_t Bh[8];
            #pragma unroll
            for (int np = 0; np < 2; ++np) {
                const uint32_t off = sw128((uint32_t)((b_row + np * 16) * 128 + ks * 32 + b_kb));
                LDSM4(&Bh[np * 4], bh + off);
            }
            #pragma unroll
            for (int mt = 0; mt < 4; ++mt)
                #pragma unroll
                for (int nt = 0; nt < 4; ++nt)
                    MMA16816(acc[mt][nt], Ahf[mt], Bh[nt * 2], Bh[nt * 2 + 1]);
        }
        __syncthreads();
    }

    if (fuse_sm) {
        float* sm = (float*)dynsmem;   // 128 rows x stride 130
        #pragma unroll
        for (int mt = 0; mt < 4; ++mt) {
            const int r0 = warp_m * 64 + mt * 16 + (lid >> 2);
            #pragma unroll
            for (int nt = 0; nt < 4; ++nt) {
                const int cit = warp_n * 32 + nt * 8 + ((lid & 3) << 1);
                const float b0 = g_bp[wrow + cit], b1 = g_bp[wrow + cit + 1];
                sm[r0 * 130 + cit]           = acc[mt][nt][0] + b0;
                sm[r0 * 130 + cit + 1]       = acc[mt][nt][1] + b1;
                sm[(r0 + 8) * 130 + cit]     = acc[mt][nt][2] + b0;
                sm[(r0 + 8) * 130 + cit + 1] = acc[mt][nt][3] + b1;
            }
        }
        __syncthreads();
        __half* op = (__half*)outp;
        #pragma unroll
        for (int rr = 0; rr < 16; ++rr) {
            const int r = wid * 16 + rr;
            #pragma unroll
            for (int g = 0; g < 2; ++g) {
                float a = sm[r * 130 + g * 64 + lid];
                float b = sm[r * 130 + g * 64 + lid + 32];
                float m = fmaxf(a, b);
                #pragma unroll
                for (int o = 16; o > 0; o >>= 1)
                    m = fmaxf(m, __shfl_xor_sync(0xffffffffu, m, o));
                float ea = __expf(a - m), eb = __expf(b - m);
                float s = ea + eb;
                #pragma unroll
                for (int o = 16; o > 0; o >>= 1)
                    s += __shfl_xor_sync(0xffffffffu, s, o);
                const float inv = 1.0f / s;
                __half* p = op + (size_t)(bm + r) * EDIM + bn + g * 64;
                p[lid]      = __float2half_rn(ea * inv);
                p[lid + 32] = __float2half_rn(eb * inv);
            }
        }
    } else if (fp16_out) {
        __half* op = (__half*)outp;
        #pragma unroll
        for (int mt = 0; mt < 4; ++mt) {
            const int r0 = bm + warp_m * 64 + mt * 16 + (lid >> 2);
            #pragma unroll
            for (int nt = 0; nt < 4; ++nt) {
                const int cit = warp_n * 32 + nt * 8 + ((lid & 3) << 1);
                const float b0 = g_bp[wrow + cit], b1 = g_bp[wrow + cit + 1];
                const int col = bn + cit;
                *(__half2*)(op + (size_t)r0 * EDIM + col) =
                    __floats2half2_rn(acc[mt][nt][0] + b0, acc[mt][nt][1] + b1);
                *(__half2*)(op + (size_t)(r0 + 8) * EDIM + col) =
                    __floats2half2_rn(acc[mt][nt][2] + b0, acc[mt][nt][3] + b1);
            }
        }
    } else {
        float* op = (float*)outp;
        #pragma unroll
        for (int mt = 0; mt < 4; ++mt) {
            const int r0 = bm + warp_m * 64 + mt * 16 + (lid >> 2);
            #pragma unroll
            for (int nt = 0; nt < 4; ++nt) {
                const int cit = warp_n * 32 + nt * 8 + ((lid & 3) << 1);
                const float b0 = g_bp[wrow + cit], b1 = g_bp[wrow + cit + 1];
                const int col = bn + cit;
                *(float2*)(op + (size_t)r0 * EDIM + col) =
                    make_float2(acc[mt][nt][0] + b0, acc[mt][nt][1] + b1);
                *(float2*)(op + (size_t)(r0 + 8) * EDIM + col) =
                    make_float2(acc[mt][nt][2] + b0, acc[mt][nt][3] + b1);
            }
        }
    }
}

// ======== MMA stats with fused last-block reduction ========
// grid (NCHUNK, 32) = 256 blocks; NT=4 tiles per chunk, double buffered.
__global__ __launch_bounds__(256, 2)
void stats_mma_kernel()
{
    __shared__ __align__(1024) char smem[2 * 16384];
    __shared__ int s_last;
    const int n = blockIdx.y, b = n >> 3, h = n & 7;
    const int s0 = blockIdx.x * S_PER_CHUNK;
    const uint32_t sb = smem_u32(smem);
    const int tid = threadIdx.x, wid = tid >> 5, lid = tid & 31;
    const int warp_m = wid >> 2;
    const int warp_n = wid & 3;

    auto issue = [&](int t, int buf) {
        const uint32_t kb = sb + buf * 16384;
        const uint32_t vb = kb + 8192;
        #pragma unroll
        for (int it = 0; it < 2; ++it) {
            const int g = tid + it * 256;
            const int r = g >> 3, cg = g & 7;
            const int s = s0 + t * S_TILE + r;
            const size_t go = (size_t)(s * 4 + b) * EDIM + h * 64 + cg * 8;
            const uint32_t so = sw128((uint32_t)(r * 128 + cg * 16));
            CP16(kb + so, g_kh + go);
            CP16(vb + so, g_vh + go);
        }
        CP_COMMIT();
    };

    float acc[2][2][4] = {};
    float colsum = 0.f;   // threads 0-127: ksum half, 128-255: vsum half

    const int a_row = (lid & 7) + ((lid >> 4) & 1) * 8;
    const int a_by  = ((lid >> 3) & 1) * 16;
    const int b_row = (lid & 7) + ((lid >> 3) & 1) * 8;
    const int b_by  = ((lid >> 4) & 1) * 16;

    issue(0, 0);
    issue(1, 1);

    const int NT = S_PER_CHUNK / S_TILE;   // 4
    for (int t = 0; t < NT; ++t) {
        if (t < NT - 1) CP_WAIT1(); else CP_WAIT0();
        __syncthreads();
        const uint32_t kb = sb + (t & 1) * 16384;
        const uint32_t vb = kb + 8192;

        #pragma unroll
        for (int ks = 0; ks < 4; ++ks) {
            uint32_t Af[2][4];
            #pragma unroll
            for (int mt = 0; mt < 2; ++mt) {
                const uint32_t off = sw128((uint32_t)((ks * 16 + a_row) * 128
                                     + warp_m * 64 + mt * 32 + a_by));
                LDSM4T(Af[mt], kb + off);
            }
            uint32_t Bf[4];
            {
                const uint32_t off = sw128((uint32_t)((ks * 16 + b_row) * 128
                                     + warp_n * 32 + b_by));
                LDSM4T(Bf, vb + off);
            }
            #pragma unroll
            for (int mt = 0; mt < 2; ++mt)
                #pragma unroll
                for (int nt = 0; nt < 2; ++nt)
                    MMA16816(acc[mt][nt], Af[mt], Bf[nt * 2], Bf[nt * 2 + 1]);
        }

        // column sums: all 256 threads; 2 threads per column, 32 rows each
        {
            const uint32_t base = (tid < 128) ? kb : vb;
            const int tt = tid & 127;
            const int d  = tt >> 1;        // column 0..63
            const int rh = (tt & 1) * 32;  // row half
            float s = 0.f;
            #pragma unroll
            for (int r = 0; r < 32; ++r)
                s += __half2float(*(const __half*)(smem + (base - sb)
                        + sw128((uint32_t)((rh + r) * 128 + d * 2))));
            colsum += s;
        }
        __syncthreads();
        if (t + 2 < NT) issue(t + 2, t & 1);
    }

    float* pb = g_part + (size_t)(n * NCHUNK + blockIdx.x) * 4224;
    #pragma unroll
    for (int mt = 0; mt < 2; ++mt) {
        const int d1 = warp_m * 32 + mt * 16 + (lid >> 2);
        #pragma unroll
        for (int nt = 0; nt < 2; ++nt) {
            const int d2 = warp_n * 16 + nt * 8 + ((lid & 3) << 1);
            *(float2*)(pb + d1 * 64 + d2)       = make_float2(acc[mt][nt][0], acc[mt][nt][1]);
            *(float2*)(pb + (d1 + 8) * 64 + d2) = make_float2(acc[mt][nt][2], acc[mt][nt][3]);
        }
    }
    // combine row halves: partner lanes 2d, 2d+1 are adjacent
    colsum += __shfl_xor_sync(0xffffffffu, colsum, 1);
    if (((tid & 127) & 1) == 0) {
        const int d = (tid & 127) >> 1;
        if (tid < 128) pb[4096 + d] = colsum;
        else           pb[4160 + d] = colsum;
    }

    __syncthreads();
    __threadfence();
    if (tid == 0) {
        const unsigned v = atomicAdd(&g_cnt[n], 1u);
        s_last = (v == NCHUNK - 1);
    }
    __syncthreads();
    if (s_last) {
        for (int j = tid; j < 4224; j += 256) {
            float s = 0.f;
            #pragma unroll
            for (int c = 0; c < NCHUNK; ++c)
                s += g_part[(size_t)(n * NCHUNK + c) * 4224 + j];
            if (j < 4096)       g_Mh[n * 4096 + j] = __float2half_rn(s);
            else if (j < 4160)  g_ksum[n * 64 + (j - 4096)] = s;
            else                g_vsum[n * 64 + (j - 4160)] = s;
        }
        if (tid == 0) g_cnt[n] = 0;
    }
}

// ======== MMA combine: a = (62*Vsum + 2*q@M) / (62*2048 + 2*q.Ksum), fp16 ====
// grid (32, 32): 64 l-rows x 64 d2 per block. Coalesced stores via smem staging.
#define CST 144   // staging row stride in bytes
__global__ __launch_bounds__(256)
void combine_mma_kernel()
{
    __shared__ __align__(1024) char smem[8192 + 8192];  // q 8K | M 8K; reused as stage
    __shared__ float ksum_s[64], vsum_s[64], inv_s[64];
    const int n = blockIdx.y, b = n >> 3, h = n & 7;
    const int l0 = blockIdx.x << 6;
    const uint32_t qb = smem_u32(smem);
    const uint32_t mb = qb + 8192;
    const int tid = threadIdx.x, wid = tid >> 5, lid = tid & 31;
    const int warp_m = wid >> 1;   // 0..3 (16 l each)
    const int warp_n = wid & 1;    // 0..1 (32 d2 each)

    #pragma unroll
    for (int it = 0; it < 2; ++it) {
        const int g = tid + it * 256;
        const int r = g >> 3, cg = g & 7;
        const size_t go = (size_t)((l0 + r) * 4 + b) * EDIM + h * 64 + cg * 8;
        const uint32_t so = sw128((uint32_t)(r * 128 + cg * 16));
        CP16(qb + so, g_qh + go);
        CP16(mb + so, g_Mh + (size_t)n * 4096 + r * 64 + cg * 8);
    }
    CP_COMMIT();
    if (tid < 64) { ksum_s[tid] = g_ksum[n * 64 + tid]; vsum_s[tid] = g_vsum[n * 64 + tid]; }
    CP_WAIT0();
    __syncthreads();

    // denominator: 4 threads per row, 2x LDS.128, shfl-combine
    {
        const int row = tid >> 2;
        const int qr  = tid & 3;
        float s = 0.f;
        #pragma unroll
        for (int hh = 0; hh < 2; ++hh) {
            const uint32_t off = sw128((uint32_t)(row * 128 + qr * 32 + hh * 16));
            const uint4 v = *(const uint4*)(smem + off);
            const uint32_t w[4] = {v.x, v.y, v.z, v.w};
            const int dbase = qr * 16 + hh * 8;
            #pragma unroll
            for (int p = 0; p < 4; ++p) {
                const float2 f = __half22float2(*(const __half2*)&w[p]);
                s += f.x * ksum_s[dbase + p * 2] + f.y * ksum_s[dbase + p * 2 + 1];
            }
        }
        s += __shfl_xor_sync(0xffffffffu, s, 1);
        s += __shfl_xor_sync(0xffffffffu, s, 2);
        if (qr == 0) inv_s[row] = 1.0f / (126976.0f + 2.0f * s);
    }
    __syncthreads();

    // q @ M via MMA: 64x64x64; warp tile 16 l x 32 d2
    float acc[4][4] = {};
    const int a_row = warp_m * 16 + (lid & 7) + ((lid >> 3) & 1) * 8;
    const int a_kb  = (lid >> 4) * 16;
    const int b_row = (lid & 7) + ((lid >> 3) & 1) * 8;
    const int b_by  = ((lid >> 4) & 1) * 16;

    #pragma unroll
    for (int ks = 0; ks < 4; ++ks) {
        uint32_t Af[4];
        LDSM4(Af, qb + sw128((uint32_t)(a_row * 128 + ks * 32 + a_kb)));
        uint32_t Bf[2][4];
        #pragma unroll
        for (int hf = 0; hf < 2; ++hf)
            LDSM4T(Bf[hf], mb + sw128((uint32_t)((ks * 16 + b_row) * 128
                                 + warp_n * 64 + hf * 32 + b_by)));
        #pragma unroll
        for (int nt = 0; nt < 4; ++nt)
            MMA16816(acc[nt], Af, Bf[nt >> 1][(nt & 1) * 2], Bf[nt >> 1][(nt & 1) * 2 + 1]);
    }

    __syncthreads();   // all q/M smem reads done; reuse as staging
    {
        const int l = warp_m * 16 + (lid >> 2);
        const float i0 = inv_s[l], i1 = inv_s[l + 8];
        #pragma unroll
        for (int nt = 0; nt < 4; ++nt) {
            const int d2 = warp_n * 32 + nt * 8 + ((lid & 3) << 1);
            const float v0 = 62.f * vsum_s[d2], v1 = 62.f * vsum_s[d2 + 1];
            *(uint32_t*)(smem + l * CST + d2 * 2) =
                pack2h((v0 + 2.f * acc[nt][0]) * i0, (v1 + 2.f * acc[nt][1]) * i0);
            *(uint32_t*)(smem + (l + 8) * CST + d2 * 2) =
                pack2h((v0 + 2.f * acc[nt][2]) * i1, (v1 + 2.f * acc[nt][3]) * i1);
        }
    }
    __syncthreads();
    // coalesced copy out: 64 rows x 128B payload
    #pragma unroll
    for (int it = 0; it < 2; ++it) {
        const int idx = tid + it * 256;        // 0..511
        const int row = idx >> 3, o16 = idx & 7;
        const uint4 v = *(const uint4*)(smem + row * CST + o16 * 16);
        *(uint4*)(g_ah + (size_t)((l0 + row) * 4 + b) * EDIM + h * 64 + o16 * 8) = v;
    }
}

// ---------------- launch -----------------------------------------------------
extern "C" void kernel_launch(void* const* d_in, const int* in_sizes, int n_in,
                              void* d_out, int out_size)
{
    const float* query = (const float*)d_in[0];
    const float* Wq = (const float*)d_in[1];
    const float* bq = (const float*)d_in[2];
    const float* Wk = (const float*)d_in[3];
    const float* bk = (const float*)d_in[4];
    const float* Wv = (const float*)d_in[5];
    const float* bv = (const float*)d_in[6];
    const float* Wo = (const float*)d_in[7];
    const float* bo = (const float*)d_in[8];
    float* out = (float*)d_out;

    __half *qp, *kp, *vp, *xh, *ahp;
    cudaGetSymbolAddress((void**)&qp, g_qh);
    cudaGetSymbolAddress((void**)&kp, g_kh);
    cudaGetSymbolAddress((void**)&vp, g_vh);
    cudaGetSymbolAddress((void**)&xh, g_xh);
    cudaGetSymbolAddress((void**)&ahp, g_ah);

    static cudaStream_t s1 = nullptr;
    static cudaEvent_t ev_split = nullptr, ev_q = nullptr;
    if (!s1) {
        cudaStreamCreateWithFlags(&s1, cudaStreamNonBlocking);
        cudaEventCreateWithFlags(&ev_split, cudaEventDisableTiming);
        cudaEventCreateWithFlags(&ev_q, cudaEventDisableTiming);
        cudaFuncSetAttribute(gemm_f16, cudaFuncAttributeMaxDynamicSharedMemorySize, SMEM_DYN);
    }

    const int total = NQ4 + 4 * NW4 + EDIM;
    split_all_kernel<<<(total + 255) / 256, 256>>>(
        (const float4*)query, (const float4*)Wq, (const float4*)Wk,
        (const float4*)Wv, (const float4*)Wo, bq, bk, bv, bo);

    // fork: Q GEMM (softmax) on side stream, concurrent with KV GEMM + stats
    cudaEventRecord(ev_split, 0);
    cudaStreamWaitEvent(s1, ev_split, 0);
    gemm_f16<<<dim3(4, 64), 256, SMEM_DYN, s1>>>(xh, 0, 1, 1, qp, qp, qp);
    cudaEventRecord(ev_q, s1);

    // legacy stream: K (softmax) + V GEMM, then stats
    gemm_f16<<<dim3(8, 64), 256, SMEM_DYN>>>(xh, 512, 1, 1, kp, vp, vp);
    stats_mma_kernel<<<dim3(NCHUNK, 32), 256>>>();

    // join: combine needs q + stats
    cudaStreamWaitEvent(0, ev_q, 0);
    combine_mma_kernel<<<dim3(32, 32), 256>>>();
    // O GEMM (fp32 output)
    gemm_f16<<<dim3(4, 64), 256, SMEM_DYN>>>(ahp, 3 * EDIM, 0, 0, out, out, out);
}

// round 17
// speedup vs baseline: 1.0608x; 1.0382x over previous
#include <cuda_runtime.h>
#include <cuda_fp16.h>
#include <cstdint>

#define EDIM   512
#define MROWS  8192
#define NCHUNK 4
#define S_PER_CHUNK 512
#define S_TILE 64

// ---------------- scratch (no allocation allowed) ----------------
__device__ __half g_qh[MROWS * EDIM];
__device__ __half g_kh[MROWS * EDIM];
__device__ __half g_vh[MROWS * EDIM];
__device__ float g_part[32 * NCHUNK * 4224];
__device__ __half g_Mh[32 * 4096];
__device__ float g_ksum[32 * 64];
__device__ float g_vsum[32 * 64];
__device__ unsigned g_cnt[32];             // zero-init; self-resetting
__device__ __half g_xh[MROWS * EDIM];      // query fp16
__device__ __half g_wh[4 * EDIM * EDIM];   // Wq|Wk|Wv|Wo fp16
__device__ __half g_ah[MROWS * EDIM];      // attention-out fp16
__device__ float g_bp[4 * EDIM];

// =================== helpers ===================
__device__ __forceinline__ uint32_t smem_u32(const void* p) {
    uint32_t a;
    asm("{ .reg .u64 t; cvta.to.shared.u64 t, %1; cvt.u32.u64 %0, t; }" : "=r"(a) : "l"(p));
    return a;
}
__device__ __forceinline__ uint32_t sw128(uint32_t off) { return off ^ ((off >> 3) & 0x70); }

__device__ __forceinline__ uint32_t pack2h(float a, float b) {
    __half2 h = __floats2half2_rn(a, b);
    return *(uint32_t*)&h;
}
#define LDSM4(r, addr) \
    asm volatile("ldmatrix.sync.aligned.m8n8.x4.shared.b16 {%0,%1,%2,%3}, [%4];" \
        : "=r"((r)[0]), "=r"((r)[1]), "=r"((r)[2]), "=r"((r)[3]) : "r"(addr))
#define LDSM4T(r, addr) \
    asm volatile("ldmatrix.sync.aligned.m8n8.x4.trans.shared.b16 {%0,%1,%2,%3}, [%4];" \
        : "=r"((r)[0]), "=r"((r)[1]), "=r"((r)[2]), "=r"((r)[3]) : "r"(addr))
#define MMA16816(d, a, b0, b1) \
    asm volatile("mma.sync.aligned.m16n8k16.row.col.f32.f16.f16.f32 " \
        "{%0,%1,%2,%3},{%4,%5,%6,%7},{%8,%9},{%0,%1,%2,%3};" \
        : "+f"((d)[0]), "+f"((d)[1]), "+f"((d)[2]), "+f"((d)[3]) \
        : "r"((a)[0]), "r"((a)[1]), "r"((a)[2]), "r"((a)[3]), "r"(b0), "r"(b1))
#define CP16(saddr, gptr) \
    asm volatile("cp.async.cg.shared.global [%0], [%1], 16;" :: "r"(saddr), "l"(gptr))
#define CP_COMMIT() asm volatile("cp.async.commit_group;" ::: "memory")
#define CP_WAIT2()  asm volatile("cp.async.wait_group 2;" ::: "memory")
#define CP_WAIT1()  asm volatile("cp.async.wait_group 1;" ::: "memory")
#define CP_WAIT0()  asm volatile("cp.async.wait_group 0;" ::: "memory")

// ------------- one fused fp32 -> fp16 conversion for ALL operands -------------
#define NQ4  (MROWS * EDIM / 4)
#define NW4  (EDIM * EDIM / 4)
__global__ void split_all_kernel(const float4* __restrict__ q,
                                 const float4* __restrict__ wq, const float4* __restrict__ wk,
                                 const float4* __restrict__ wv, const float4* __restrict__ wo,
                                 const float* __restrict__ bq, const float* __restrict__ bk,
                                 const float* __restrict__ bv, const float* __restrict__ bo)
{
    const int i = blockIdx.x * blockDim.x + threadIdx.x;
    const int total = NQ4 + 4 * NW4;
    if (i < NQ4) {
        const float4 x = q[i];
        ((uint2*)g_xh)[i] = make_uint2(pack2h(x.x, x.y), pack2h(x.z, x.w));
    } else if (i < total) {
        const int j = i - NQ4;
        const int w = j / NW4, off = j % NW4;
        const float4* src = (w == 0) ? wq : (w == 1) ? wk : (w == 2) ? wv : wo;
        const float4 x = src[off];
        ((uint2*)g_wh)[j] = make_uint2(pack2h(x.x, x.y), pack2h(x.z, x.w));
    } else if (i < total + EDIM) {
        const int t = i - total;
        g_bp[t] = bq[t];
        g_bp[EDIM + t] = bk[t];
        g_bp[2 * EDIM + t] = bv[t];
        g_bp[3 * EDIM + t] = bo[t];
    }
}

// ======== fp16 single-pass warp-MMA GEMM, 3-stage cp.async pipeline ========
#define STAGE_BYTES 32768
#define SMEM_DYN (3 * STAGE_BYTES)

extern __shared__ __align__(1024) char dynsmem[];

__global__ __launch_bounds__(256, 2)
void gemm_f16(const __half* __restrict__ Ah,
              int wbase, int n_soft, int fp16_out,
              void* __restrict__ out0, void* __restrict__ out1, void* __restrict__ out2)
{
    const uint32_t sbase = smem_u32(dynsmem);
    const int tid = threadIdx.x;
    const int wid = tid >> 5, lid = tid & 31;
    const int warp_m = wid >> 2;
    const int warp_n = wid & 3;
    const int nb = blockIdx.x;
    const int bm = blockIdx.y << 7;
    const int bn = (nb & 3) << 7;
    const int sel = nb >> 2;
    void* outp = (sel == 0) ? out0 : ((sel == 1) ? out1 : out2);
    const int wrow = wbase + nb * 128;
    const int fuse_sm = (sel < n_soft);

    int cp_r[4], cp_cg[4];
    uint32_t cp_soff[4];
    #pragma unroll
    for (int it = 0; it < 4; ++it) {
        const int g = tid + it * 256;
        cp_r[it] = g >> 3;
        cp_cg[it] = g & 7;
        cp_soff[it] = sw128((uint32_t)(cp_r[it] * 128 + cp_cg[it] * 16));
    }

    float acc[4][4][4] = {};
    const int a_row = warp_m * 64 + (lid & 7) + ((lid >> 3) & 1) * 8;
    const int a_kb  = (lid >> 4) * 16;
    const int b_row = warp_n * 32 + (lid & 7) + (lid >> 4) * 8;
    const int b_kb  = ((lid >> 3) & 1) * 16;

    auto issue = [&](int c, int buf) {
        const uint32_t ah = sbase + buf * STAGE_BYTES;
        const uint32_t bh = ah + 16384;
        const int kof = c * 64;
        #pragma unroll
        for (int it = 0; it < 4; ++it) {
            const size_t aoff = (size_t)(bm + cp_r[it]) * EDIM + kof + cp_cg[it] * 8;
            const size_t boff = (size_t)(wrow + cp_r[it]) * EDIM + kof + cp_cg[it] * 8;
            CP16(ah + cp_soff[it], Ah + aoff);
            CP16(bh + cp_soff[it], g_wh + boff);
        }
        CP_COMMIT();
    };

    issue(0, 0);
    issue(1, 1);

    for (int c = 0; c < 8; ++c) {
        if (c + 2 < 8) { issue(c + 2, (c + 2) % 3); CP_WAIT2(); }
        else if (c + 1 < 8) { CP_WAIT1(); }
        else { CP_WAIT0(); }
        __syncthreads();

        const uint32_t ah = sbase + (c % 3) * STAGE_BYTES;
        const uint32_t bh = ah + 16384;

        #pragma unroll
        for (int ks = 0; ks < 4; ++ks) {
            uint32_t Ahf[4][4];
            #pragma unroll
            for (int mt = 0; mt < 4; ++mt) {
                const uint32_t off = sw128((uint32_t)((a_row + mt * 16) * 128 + ks * 32 + a_kb));
                LDSM4(Ahf[mt], ah + off);
            }
            uint32_t Bh[8];
            #pragma unroll
            for (int np = 0; np < 2; ++np) {
                const uint32_t off = sw128((uint32_t)((b_row + np * 16) * 128 + ks * 32 + b_kb));
                LDSM4(&Bh[np * 4], bh + off);
            }
            #pragma unroll
            for (int mt = 0; mt < 4; ++mt)
                #pragma unroll
                for (int nt = 0; nt < 4; ++nt)
                    MMA16816(acc[mt][nt], Ahf[mt], Bh[nt * 2], Bh[nt * 2 + 1]);
        }
        __syncthreads();
    }

    if (fuse_sm) {
        float* sm = (float*)dynsmem;   // 128 rows x stride 130
        #pragma unroll
        for (int mt = 0; mt < 4; ++mt) {
            const int r0 = warp_m * 64 + mt * 16 + (lid >> 2);
            #pragma unroll
            for (int nt = 0; nt < 4; ++nt) {
                const int cit = warp_n * 32 + nt * 8 + ((lid & 3) << 1);
                const float b0 = g_bp[wrow + cit], b1 = g_bp[wrow + cit + 1];
                sm[r0 * 130 + cit]           = acc[mt][nt][0] + b0;
                sm[r0 * 130 + cit + 1]       = acc[mt][nt][1] + b1;
                sm[(r0 + 8) * 130 + cit]     = acc[mt][nt][2] + b0;
                sm[(r0 + 8) * 130 + cit + 1] = acc[mt][nt][3] + b1;
            }
        }
        __syncthreads();
        __half* op = (__half*)outp;
        #pragma unroll
        for (int rr = 0; rr < 16; ++rr) {
            const int r = wid * 16 + rr;
            #pragma unroll
            for (int g = 0; g < 2; ++g) {
                float a = sm[r * 130 + g * 64 + lid];
                float b = sm[r * 130 + g * 64 + lid + 32];
                float m = fmaxf(a, b);
                #pragma unroll
                for (int o = 16; o > 0; o >>= 1)
                    m = fmaxf(m, __shfl_xor_sync(0xffffffffu, m, o));
                float ea = __expf(a - m), eb = __expf(b - m);
                float s = ea + eb;
                #pragma unroll
                for (int o = 16; o > 0; o >>= 1)
                    s += __shfl_xor_sync(0xffffffffu, s, o);
                const float inv = 1.0f / s;
                __half* p = op + (size_t)(bm + r) * EDIM + bn + g * 64;
                p[lid]      = __float2half_rn(ea * inv);
                p[lid + 32] = __float2half_rn(eb * inv);
            }
        }
    } else if (fp16_out) {
        __half* op = (__half*)outp;
        #pragma unroll
        for (int mt = 0; mt < 4; ++mt) {
            const int r0 = bm + warp_m * 64 + mt * 16 + (lid >> 2);
            #pragma unroll
            for (int nt = 0; nt < 4; ++nt) {
                const int cit = warp_n * 32 + nt * 8 + ((lid & 3) << 1);
                const float b0 = g_bp[wrow + cit], b1 = g_bp[wrow + cit + 1];
                const int col = bn + cit;
                *(__half2*)(op + (size_t)r0 * EDIM + col) =
                    __floats2half2_rn(acc[mt][nt][0] + b0, acc[mt][nt][1] + b1);
                *(__half2*)(op + (size_t)(r0 + 8) * EDIM + col) =
                    __floats2half2_rn(acc[mt][nt][2] + b0, acc[mt][nt][3] + b1);
            }
        }
    } else {
        float* op = (float*)outp;
        #pragma unroll
        for (int mt = 0; mt < 4; ++mt) {
            const int r0 = bm + warp_m * 64 + mt * 16 + (lid >> 2);
            #pragma unroll
            for (int nt = 0; nt < 4; ++nt) {
                const int cit = warp_n * 32 + nt * 8 + ((lid & 3) << 1);
                const float b0 = g_bp[wrow + cit], b1 = g_bp[wrow + cit + 1];
                const int col = bn + cit;
                *(float2*)(op + (size_t)r0 * EDIM + col) =
                    make_float2(acc[mt][nt][0] + b0, acc[mt][nt][1] + b1);
                *(float2*)(op + (size_t)(r0 + 8) * EDIM + col) =
                    make_float2(acc[mt][nt][2] + b0, acc[mt][nt][3] + b1);
            }
        }
    }
}

// ======== MMA stats with fused last-block reduction ========
// grid (NCHUNK, 32) = 128 blocks; NT=8 tiles, double buffered.
// ksum/vsum via ones-operand MMA (no serial column scan).
__global__ __launch_bounds__(256, 2)
void stats_mma_kernel()
{
    __shared__ __align__(1024) char smem[2 * 16384];
    __shared__ int s_last;
    const int n = blockIdx.y, b = n >> 3, h = n & 7;
    const int s0 = blockIdx.x * S_PER_CHUNK;
    const uint32_t sb = smem_u32(smem);
    const int tid = threadIdx.x, wid = tid >> 5, lid = tid & 31;
    const int warp_m = wid >> 2;
    const int warp_n = wid & 3;

    auto issue = [&](int t, int buf) {
        const uint32_t kb = sb + buf * 16384;
        const uint32_t vb = kb + 8192;
        #pragma unroll
        for (int it = 0; it < 2; ++it) {
            const int g = tid + it * 256;
            const int r = g >> 3, cg = g & 7;
            const int s = s0 + t * S_TILE + r;
            const size_t go = (size_t)(s * 4 + b) * EDIM + h * 64 + cg * 8;
            const uint32_t so = sw128((uint32_t)(r * 128 + cg * 16));
            CP16(kb + so, g_kh + go);
            CP16(vb + so, g_vh + go);
        }
        CP_COMMIT();
    };

    float acc[2][2][4] = {};
    float acc_cs[2][4] = {};                 // column sums via MMA
    const uint32_t ONES[4] = {0x3C003C00u, 0x3C003C00u, 0x3C003C00u, 0x3C003C00u};

    const int a_row = (lid & 7) + ((lid >> 4) & 1) * 8;
    const int a_by  = ((lid >> 3) & 1) * 16;
    const int b_row = (lid & 7) + ((lid >> 3) & 1) * 8;
    const int b_by  = ((lid >> 4) & 1) * 16;
    const int cs_col = (wid & 3) * 32;       // byte offset of this warp's 16-col slice

    issue(0, 0);
    issue(1, 1);

    const int NT = S_PER_CHUNK / S_TILE;   // 8
    for (int t = 0; t < NT; ++t) {
        if (t < NT - 1) CP_WAIT1(); else CP_WAIT0();
        __syncthreads();
        const uint32_t kb = sb + (t & 1) * 16384;
        const uint32_t vb = kb + 8192;
        const uint32_t cs_base = (wid < 4) ? kb : vb;   // warps 0-3: ksum, 4-7: vsum

        #pragma unroll
        for (int ks = 0; ks < 4; ++ks) {
            uint32_t Af[2][4];
            #pragma unroll
            for (int mt = 0; mt < 2; ++mt) {
                const uint32_t off = sw128((uint32_t)((ks * 16 + a_row) * 128
                                     + warp_m * 64 + mt * 32 + a_by));
                LDSM4T(Af[mt], kb + off);
            }
            uint32_t Bf[4];
            {
                const uint32_t off = sw128((uint32_t)((ks * 16 + b_row) * 128
                                     + warp_n * 32 + b_by));
                LDSM4T(Bf, vb + off);
            }
            #pragma unroll
            for (int mt = 0; mt < 2; ++mt)
                #pragma unroll
                for (int nt = 0; nt < 2; ++nt)
                    MMA16816(acc[mt][nt], Af[mt], Bf[nt * 2], Bf[nt * 2 + 1]);

            // column sums: ones^T @ tile -> replicated row of sums
            uint32_t Cf[4];
            {
                const uint32_t off = sw128((uint32_t)((ks * 16 + b_row) * 128
                                     + cs_col + b_by));
                LDSM4T(Cf, cs_base + off);
            }
            MMA16816(acc_cs[0], ONES, Cf[0], Cf[1]);
            MMA16816(acc_cs[1], ONES, Cf[2], Cf[3]);
        }
        __syncthreads();
        if (t + 2 < NT) issue(t + 2, t & 1);
    }

    float* pb = g_part + (size_t)(n * NCHUNK + blockIdx.x) * 4224;
    #pragma unroll
    for (int mt = 0; mt < 2; ++mt) {
        const int d1 = warp_m * 32 + mt * 16 + (lid >> 2);
        #pragma unroll
        for (int nt = 0; nt < 2; ++nt) {
            const int d2 = warp_n * 16 + nt * 8 + ((lid & 3) << 1);
            *(float2*)(pb + d1 * 64 + d2)       = make_float2(acc[mt][nt][0], acc[mt][nt][1]);
            *(float2*)(pb + (d1 + 8) * 64 + d2) = make_float2(acc[mt][nt][2], acc[mt][nt][3]);
        }
    }
    // colsum rows are replicated; lanes 0-3 (row 0) hold cols 2*(lid&3), +1
    if (lid < 4) {
        const int base = (wid < 4) ? 4096 : 4160;
        const int d = (wid & 3) * 16;
        #pragma unroll
        for (int nt = 0; nt < 2; ++nt) {
            pb[base + d + nt * 8 + lid * 2]     = acc_cs[nt][0];
            pb[base + d + nt * 8 + lid * 2 + 1] = acc_cs[nt][1];
        }
    }

    __syncthreads();
    __threadfence();
    if (tid == 0) {
        const unsigned v = atomicAdd(&g_cnt[n], 1u);
        s_last = (v == NCHUNK - 1);
    }
    __syncthreads();
    if (s_last) {
        for (int j = tid; j < 4224; j += 256) {
            float s = 0.f;
            #pragma unroll
            for (int c = 0; c < NCHUNK; ++c)
                s += g_part[(size_t)(n * NCHUNK + c) * 4224 + j];
            if (j < 4096)       g_Mh[n * 4096 + j] = __float2half_rn(s);
            else if (j < 4160)  g_ksum[n * 64 + (j - 4096)] = s;
            else                g_vsum[n * 64 + (j - 4160)] = s;
        }
        if (tid == 0) g_cnt[n] = 0;
    }
}

// ======== MMA combine: a = (62*Vsum + 2*q@M) / (62*2048 + 2*q.Ksum), fp16 ====
// grid (32, 32): 64 l-rows x 64 d2 per block. Coalesced stores via smem staging.
#define CST 144   // staging row stride in bytes
__global__ __launch_bounds__(256)
void combine_mma_kernel()
{
    __shared__ __align__(1024) char smem[8192 + 8192];  // q 8K | M 8K; reused as stage
    __shared__ float ksum_s[64], vsum_s[64], inv_s[64];
    const int n = blockIdx.y, b = n >> 3, h = n & 7;
    const int l0 = blockIdx.x << 6;
    const uint32_t qb = smem_u32(smem);
    const uint32_t mb = qb + 8192;
    const int tid = threadIdx.x, wid = tid >> 5, lid = tid & 31;
    const int warp_m = wid >> 1;   // 0..3 (16 l each)
    const int warp_n = wid & 1;    // 0..1 (32 d2 each)

    #pragma unroll
    for (int it = 0; it < 2; ++it) {
        const int g = tid + it * 256;
        const int r = g >> 3, cg = g & 7;
        const size_t go = (size_t)((l0 + r) * 4 + b) * EDIM + h * 64 + cg * 8;
        const uint32_t so = sw128((uint32_t)(r * 128 + cg * 16));
        CP16(qb + so, g_qh + go);
        CP16(mb + so, g_Mh + (size_t)n * 4096 + r * 64 + cg * 8);
    }
    CP_COMMIT();
    if (tid < 64) { ksum_s[tid] = g_ksum[n * 64 + tid]; vsum_s[tid] = g_vsum[n * 64 + tid]; }
    CP_WAIT0();
    __syncthreads();

    // denominator: 4 threads per row, 2x LDS.128, shfl-combine
    {
        const int row = tid >> 2;
        const int qr  = tid & 3;
        float s = 0.f;
        #pragma unroll
        for (int hh = 0; hh < 2; ++hh) {
            const uint32_t off = sw128((uint32_t)(row * 128 + qr * 32 + hh * 16));
            const uint4 v = *(const uint4*)(smem + off);
            const uint32_t w[4] = {v.x, v.y, v.z, v.w};
            const int dbase = qr * 16 + hh * 8;
            #pragma unroll
            for (int p = 0; p < 4; ++p) {
                const float2 f = __half22float2(*(const __half2*)&w[p]);
                s += f.x * ksum_s[dbase + p * 2] + f.y * ksum_s[dbase + p * 2 + 1];
            }
        }
        s += __shfl_xor_sync(0xffffffffu, s, 1);
        s += __shfl_xor_sync(0xffffffffu, s, 2);
        if (qr == 0) inv_s[row] = 1.0f / (126976.0f + 2.0f * s);
    }
    __syncthreads();

    // q @ M via MMA: 64x64x64; warp tile 16 l x 32 d2
    float acc[4][4] = {};
    const int a_row = warp_m * 16 + (lid & 7) + ((lid >> 3) & 1) * 8;
    const int a_kb  = (lid >> 4) * 16;
    const int b_row = (lid & 7) + ((lid >> 3) & 1) * 8;
    const int b_by  = ((lid >> 4) & 1) * 16;

    #pragma unroll
    for (int ks = 0; ks < 4; ++ks) {
        uint32_t Af[4];
        LDSM4(Af, qb + sw128((uint32_t)(a_row * 128 + ks * 32 + a_kb)));
        uint32_t Bf[2][4];
        #pragma unroll
        for (int hf = 0; hf < 2; ++hf)
            LDSM4T(Bf[hf], mb + sw128((uint32_t)((ks * 16 + b_row) * 128
                                 + warp_n * 64 + hf * 32 + b_by)));
        #pragma unroll
        for (int nt = 0; nt < 4; ++nt)
            MMA16816(acc[nt], Af, Bf[nt >> 1][(nt & 1) * 2], Bf[nt >> 1][(nt & 1) * 2 + 1]);
    }

    __syncthreads();   // all q/M smem reads done; reuse as staging
    {
        const int l = warp_m * 16 + (lid >> 2);
        const float i0 = inv_s[l], i1 = inv_s[l + 8];
        #pragma unroll
        for (int nt = 0; nt < 4; ++nt) {
            const int d2 = warp_n * 32 + nt * 8 + ((lid & 3) << 1);
            const float v0 = 62.f * vsum_s[d2], v1 = 62.f * vsum_s[d2 + 1];
            *(uint32_t*)(smem + l * CST + d2 * 2) =
                pack2h((v0 + 2.f * acc[nt][0]) * i0, (v1 + 2.f * acc[nt][1]) * i0);
            *(uint32_t*)(smem + (l + 8) * CST + d2 * 2) =
                pack2h((v0 + 2.f * acc[nt][2]) * i1, (v1 + 2.f * acc[nt][3]) * i1);
        }
    }
    __syncthreads();
    // coalesced copy out: 64 rows x 128B payload
    #pragma unroll
    for (int it = 0; it < 2; ++it) {
        const int idx = tid + it * 256;        // 0..511
        const int row = idx >> 3, o16 = idx & 7;
        const uint4 v = *(const uint4*)(smem + row * CST + o16 * 16);
        *(uint4*)(g_ah + (size_t)((l0 + row) * 4 + b) * EDIM + h * 64 + o16 * 8) = v;
    }
}

// ---------------- launch -----------------------------------------------------
extern "C" void kernel_launch(void* const* d_in, const int* in_sizes, int n_in,
                              void* d_out, int out_size)
{
    const float* query = (const float*)d_in[0];
    const float* Wq = (const float*)d_in[1];
    const float* bq = (const float*)d_in[2];
    const float* Wk = (const float*)d_in[3];
    const float* bk = (const float*)d_in[4];
    const float* Wv = (const float*)d_in[5];
    const float* bv = (const float*)d_in[6];
    const float* Wo = (const float*)d_in[7];
    const float* bo = (const float*)d_in[8];
    float* out = (float*)d_out;

    __half *qp, *kp, *vp, *xh, *ahp;
    cudaGetSymbolAddress((void**)&qp, g_qh);
    cudaGetSymbolAddress((void**)&kp, g_kh);
    cudaGetSymbolAddress((void**)&vp, g_vh);
    cudaGetSymbolAddress((void**)&xh, g_xh);
    cudaGetSymbolAddress((void**)&ahp, g_ah);

    static cudaStream_t s1 = nullptr;
    static cudaEvent_t ev_split = nullptr, ev_q = nullptr;
    if (!s1) {
        cudaStreamCreateWithFlags(&s1, cudaStreamNonBlocking);
        cudaEventCreateWithFlags(&ev_split, cudaEventDisableTiming);
        cudaEventCreateWithFlags(&ev_q, cudaEventDisableTiming);
        cudaFuncSetAttribute(gemm_f16, cudaFuncAttributeMaxDynamicSharedMemorySize, SMEM_DYN);
    }

    const int total = NQ4 + 4 * NW4 + EDIM;
    split_all_kernel<<<(total + 255) / 256, 256>>>(
        (const float4*)query, (const float4*)Wq, (const float4*)Wk,
        (const float4*)Wv, (const float4*)Wo, bq, bk, bv, bo);

    // fork: Q GEMM (softmax) on side stream, concurrent with KV GEMM + stats
    cudaEventRecord(ev_split, 0);
    cudaStreamWaitEvent(s1, ev_split, 0);
    gemm_f16<<<dim3(4, 64), 256, SMEM_DYN, s1>>>(xh, 0, 1, 1, qp, qp, qp);
    cudaEventRecord(ev_q, s1);

    // legacy stream: K (softmax) + V GEMM, then stats
    gemm_f16<<<dim3(8, 64), 256, SMEM_DYN>>>(xh, 512, 1, 1, kp, vp, vp);
    stats_mma_kernel<<<dim3(NCHUNK, 32), 256>>>();

    // join: combine needs q + stats
    cudaStreamWaitEvent(0, ev_q, 0);
    combine_mma_kernel<<<dim3(32, 32), 256>>>();
    // O GEMM (fp32 output)
    gemm_f16<<<dim3(4, 64), 256, SMEM_DYN>>>(ahp, 3 * EDIM, 0, 0, out, out, out);
}